// round 13
// baseline (speedup 1.0000x reference)
#include <cuda_runtime.h>
#include <cuda_bf16.h>

// Problem: B=64, L=1024, D=1280
//   pool_len = lengths + 2
//   emb[b,d]  = mean over l < pool_len of prev[b,l,d]
//   x         = relu(emb @ dense_w + dense_b)        [64,1280]
//   out       = x @ cls_w + cls_b                    [64,1]
//
// Three launches:
//  1) pool_kernel : 1024 blocks x 320 thr, 5 blocks/SM. Exact task list over
//     valid 64-row segments. Loads via TMA 1-D bulk copies (20 KB chunks,
//     double-buffered smem) -> bypasses per-SM LDG outstanding limits.
//     Last-arriving block per b reduces partials, writes embT[k][b].
//  2) gemm_kernel : 320 blocks x 256 thr, KS=8 k-splits, FFMA2 inner loop.
//  3) final_kernel: grid(64,5) x 64 thr, k-reduce + bias + relu + cls dot,
//     atomicAdd into out (initialized by gemm block 0).

#define Bq     64
#define Lq     1024
#define Dq     1280
#define D4     320           // float4 per row
#define SEGR   64            // rows per pool segment
#define MAXSEG 16
#define RCH    4             // rows per TMA chunk
#define CHB    (RCH * Dq * 4)// chunk bytes = 20480

#define KS     8             // GEMM k-splits
#define KCH    160           // k per split
#define KC     80            // k staged per chunk
#define NJ     40            // j tiles
#define JTW    32            // j tile width

typedef unsigned long long u64;

// scratch (allocation-free: __device__ globals)
__device__ float    g_part [Bq * MAXSEG * Dq];  // pool partials (5.24 MB)
__device__ float    g_embT [Dq * Bq];           // emb transposed [k][b]
__device__ float    g_xpart[KS * Bq * Dq];      // GEMM k-partials (2.62 MB)
__device__ unsigned g_cnt  [Bq];                // arrival counters (monotonic)

// ---- PTX helpers -----------------------------------------------------------
__device__ __forceinline__ unsigned smem_u32(const void* p) {
    return (unsigned)__cvta_generic_to_shared(p);
}
__device__ __forceinline__ void mbar_init(unsigned bar) {
    asm volatile("mbarrier.init.shared.b64 [%0], 1;" :: "r"(bar) : "memory");
}
__device__ __forceinline__ void mbar_expect_tx(unsigned bar, unsigned bytes) {
    asm volatile("mbarrier.arrive.expect_tx.shared.b64 _, [%0], %1;"
                 :: "r"(bar), "r"(bytes) : "memory");
}
__device__ __forceinline__ void tma_1d(unsigned dst, const void* src,
                                       unsigned bytes, unsigned bar) {
    asm volatile(
        "cp.async.bulk.shared::cluster.global.mbarrier::complete_tx::bytes "
        "[%0], [%1], %2, [%3];"
        :: "r"(dst), "l"(src), "r"(bytes), "r"(bar) : "memory");
}
__device__ __forceinline__ void mbar_wait(unsigned bar, unsigned parity) {
    asm volatile(
        "{\n\t"
        ".reg .pred P;\n"
        "WAIT_%=:\n\t"
        "mbarrier.try_wait.parity.acquire.cta.shared::cta.b64 P, [%0], %1, 0x989680;\n\t"
        "@P bra.uni DONE_%=;\n\t"
        "bra.uni WAIT_%=;\n"
        "DONE_%=:\n\t"
        "}"
        :: "r"(bar), "r"(parity) : "memory");
}
// packed f32x2 FMA (SASS FFMA2)
__device__ __forceinline__ u64 ffma2(u64 a, u64 b, u64 c) {
    u64 d;
    asm("fma.rn.f32x2 %0, %1, %2, %3;" : "=l"(d) : "l"(a), "l"(b), "l"(c));
    return d;
}
__device__ __forceinline__ u64 pack2(float lo, float hi) {
    u64 d;
    asm("mov.b64 %0, {%1, %2};" : "=l"(d) : "f"(lo), "f"(hi));
    return d;
}
__device__ __forceinline__ void unpack2(u64 v, float& lo, float& hi) {
    asm("mov.b64 {%0, %1}, %2;" : "=f"(lo), "=f"(hi) : "l"(v));
}

// ---------------------------------------------------------------------------
// Kernel 1: TMA-fed ragged pool + fused per-b reduction.
// ---------------------------------------------------------------------------
__global__ void __launch_bounds__(D4, 5) pool_kernel(
    const float* __restrict__ prev, const int* __restrict__ lengths)
{
    __shared__ __align__(16) float sbuf[2][RCH * Dq];   // 2 x 20 KB
    __shared__ __align__(8)  u64   sbar[2];
    __shared__ int s_pre[Bq + 1];
    __shared__ int s_last;

    const int tid = threadIdx.x;

    if (tid == 0) {
        int acc = 0;
        s_pre[0] = 0;
        for (int b = 0; b < Bq; ++b) {
            int pl = lengths[b] + 2;
            acc += (pl + SEGR - 1) >> 6;
            s_pre[b + 1] = acc;
        }
    }
    __syncthreads();
    const int S = s_pre[Bq];
    const int t = blockIdx.x;
    if (t >= S) return;                          // empty block retires fast

    // binary search: b with s_pre[b] <= t < s_pre[b+1]
    int lo = 0, hi = Bq;
    while (hi - lo > 1) {
        int m = (lo + hi) >> 1;
        if (s_pre[m] <= t) lo = m; else hi = m;
    }
    const int b    = lo;
    const int seg  = t - s_pre[b];
    const int pl   = lengths[b] + 2;
    const int l0   = seg * SEGR;
    const int n    = min(SEGR, pl - l0);         // 1..64 rows
    const int nseg = s_pre[b + 1] - s_pre[b];
    const int nch  = (n + RCH - 1) >> 2;         // chunks of 4 rows

    const unsigned bar0 = smem_u32(&sbar[0]);
    const unsigned bar1 = smem_u32(&sbar[1]);
    const unsigned sb0  = smem_u32(&sbuf[0][0]);
    const unsigned sb1  = smem_u32(&sbuf[1][0]);
    const char* src_base = reinterpret_cast<const char*>(prev)
                         + ((size_t)b * Lq + l0) * Dq * 4;

    if (tid == 0) { mbar_init(bar0); mbar_init(bar1); }
    __syncthreads();

    // prime the pipeline: issue chunk 0 (and 1)
    if (tid == 0) {
        unsigned bytes0 = (unsigned)(min(RCH, n) * Dq * 4);
        mbar_expect_tx(bar0, bytes0);
        tma_1d(sb0, src_base, bytes0, bar0);
        if (nch > 1) {
            unsigned bytes1 = (unsigned)(min(RCH, n - RCH) * Dq * 4);
            mbar_expect_tx(bar1, bytes1);
            tma_1d(sb1, src_base + CHB, bytes1, bar1);
        }
    }

    float4 acc = make_float4(0.f, 0.f, 0.f, 0.f);

    for (int c = 0; c < nch; ++c) {
        const int      bufi = c & 1;
        const unsigned bar  = bufi ? bar1 : bar0;
        const unsigned par  = (unsigned)((c >> 1) & 1);
        mbar_wait(bar, par);

        const int rc = min(RCH, n - c * RCH);
        const float4* sp = reinterpret_cast<const float4*>(&sbuf[bufi][0]) + tid;
#pragma unroll
        for (int r = 0; r < RCH; ++r) {
            if (r < rc) {
                float4 v = sp[r * D4];
                acc.x += v.x; acc.y += v.y; acc.z += v.z; acc.w += v.w;
            }
        }
        __syncthreads();                         // all consumed before reuse

        if (tid == 0 && c + 2 < nch) {           // refill this buffer
            unsigned bytes = (unsigned)(min(RCH, n - (c + 2) * RCH) * Dq * 4);
            mbar_expect_tx(bar, bytes);
            tma_1d(bufi ? sb1 : sb0, src_base + (size_t)(c + 2) * CHB, bytes, bar);
        }
    }

    reinterpret_cast<float4*>(g_part)[((size_t)b * MAXSEG + seg) * D4 + tid] = acc;

    // publish partial; last arrival for b reduces + writes embT
    __threadfence();
    __syncthreads();
    if (tid == 0) {
        unsigned old = atomicAdd(&g_cnt[b], 1u);
        s_last = (((old + 1u) % (unsigned)nseg) == 0u) ? 1 : 0;
    }
    __syncthreads();
    if (s_last) {
        __threadfence();                         // acquire peers' partials
        const float4* gp = reinterpret_cast<const float4*>(g_part)
                           + (size_t)b * MAXSEG * D4 + tid;
        float4 r = make_float4(0.f, 0.f, 0.f, 0.f);
        for (int sg = 0; sg < nseg; ++sg) {
            float4 v = gp[(size_t)sg * D4];
            r.x += v.x; r.y += v.y; r.z += v.z; r.w += v.w;
        }
        const float inv = 1.0f / (float)pl;
        r.x *= inv; r.y *= inv; r.z *= inv; r.w *= inv;
        g_embT[(size_t)(4 * tid + 0) * Bq + b] = r.x;
        g_embT[(size_t)(4 * tid + 1) * Bq + b] = r.y;
        g_embT[(size_t)(4 * tid + 2) * Bq + b] = r.z;
        g_embT[(size_t)(4 * tid + 3) * Bq + b] = r.w;
    }
}

// ---------------------------------------------------------------------------
// Kernel 2: k-split GEMM (KS=8), FFMA2. grid 320 = ky*NJ + jx, 256 threads.
// Block tile 64b x 32j x 160k; thread 2b x 4j. Block 0 inits out[b] = cls_b.
// ---------------------------------------------------------------------------
__global__ void __launch_bounds__(256) gemm_kernel(
    const float* __restrict__ W, const float* __restrict__ cls_b,
    float* __restrict__ out)
{
    __shared__ __align__(16) float sE[KC][Bq];    // 20 KB
    __shared__ __align__(16) float sW[KC][JTW];   // 10 KB

    const int tid = threadIdx.x;
    const int ky  = blockIdx.x / NJ;              // 0..7
    const int jx  = blockIdx.x % NJ;              // 0..39
    const int k0  = ky * KCH;
    const int j0  = jx * JTW;
    const int bg  = tid >> 3;                     // 0..31 -> b = 2bg, 2bg+1
    const int jg  = tid & 7;                      // 0..7  -> j = 4jg..4jg+3

    if (blockIdx.x == 0 && tid < Bq)              // init out for final's atomics
        out[tid] = cls_b[0];

    u64 a00 = 0ull, a01 = 0ull, a10 = 0ull, a11 = 0ull;

    for (int c = 0; c < KCH; c += KC) {
        __syncthreads();
        for (int i = tid; i < KC * Bq; i += 256) {
            int kk = i >> 6;
            int bb = i & 63;
            sE[kk][bb] = g_embT[(size_t)(k0 + c + kk) * Bq + bb];
        }
        for (int i = tid; i < KC * JTW; i += 256) {
            int kk = i >> 5;
            int jj = i & 31;
            sW[kk][jj] = W[(size_t)(k0 + c + kk) * Dq + j0 + jj];
        }
        __syncthreads();

#pragma unroll 10
        for (int kk = 0; kk < KC; ++kk) {
            float2 e  = *reinterpret_cast<const float2*>(&sE[kk][2 * bg]);
            float4 w  = *reinterpret_cast<const float4*>(&sW[kk][4 * jg]);
            u64 e0  = pack2(e.x, e.x);
            u64 e1  = pack2(e.y, e.y);
            u64 w01 = pack2(w.x, w.y);
            u64 w23 = pack2(w.z, w.w);
            a00 = ffma2(e0, w01, a00);
            a01 = ffma2(e0, w23, a01);
            a10 = ffma2(e1, w01, a10);
            a11 = ffma2(e1, w23, a11);
        }
    }

    float x0, y0, z0, w0f, x1, y1, z1, w1f;
    unpack2(a00, x0, y0); unpack2(a01, z0, w0f);
    unpack2(a10, x1, y1); unpack2(a11, z1, w1f);
    const int b0 = 2 * bg;
    float* dst0 = &g_xpart[((size_t)ky * Bq + b0) * Dq + j0 + 4 * jg];
    *reinterpret_cast<float4*>(dst0)      = make_float4(x0, y0, z0, w0f);
    *reinterpret_cast<float4*>(dst0 + Dq) = make_float4(x1, y1, z1, w1f);
}

// ---------------------------------------------------------------------------
// Kernel 3: reduce k-partials, +bias, relu, dot cls_w, atomicAdd.
// grid(64, 5), 64 threads.
// ---------------------------------------------------------------------------
__global__ void __launch_bounds__(64) final_kernel(
    const float* __restrict__ dense_b,
    const float* __restrict__ cls_w,
    float* __restrict__ out)
{
    const int b   = blockIdx.x;
    const int tid = threadIdx.x;
    const int d4  = blockIdx.y * 64 + tid;        // 0..319
    const float4* xp = reinterpret_cast<const float4*>(g_xpart);

    float4 s = reinterpret_cast<const float4*>(dense_b)[d4];
#pragma unroll
    for (int ks = 0; ks < KS; ++ks) {
        float4 v = xp[((size_t)ks * Bq + b) * D4 + d4];
        s.x += v.x; s.y += v.y; s.z += v.z; s.w += v.w;
    }
    s.x = fmaxf(s.x, 0.f); s.y = fmaxf(s.y, 0.f);
    s.z = fmaxf(s.z, 0.f); s.w = fmaxf(s.w, 0.f);

    float4 w = reinterpret_cast<const float4*>(cls_w)[d4];
    float part = s.x * w.x + s.y * w.y + s.z * w.z + s.w * w.w;

#pragma unroll
    for (int o = 16; o > 0; o >>= 1)
        part += __shfl_down_sync(0xffffffffu, part, o);
    if ((tid & 31) == 0)
        atomicAdd(&out[b], part);                 // 10 adds per b total
}

// ---------------------------------------------------------------------------
extern "C" void kernel_launch(void* const* d_in, const int* in_sizes, int n_in,
                              void* d_out, int out_size)
{
    const float* prev    = (const float*)d_in[0];
    const int*   lengths = (const int*)  d_in[1];
    const float* dense_w = (const float*)d_in[2];
    const float* dense_b = (const float*)d_in[3];
    const float* cls_w   = (const float*)d_in[4];
    const float* cls_b   = (const float*)d_in[5];
    float*       out     = (float*)d_out;

    pool_kernel <<<Bq * MAXSEG, D4>>>(prev, lengths);
    gemm_kernel <<<KS * NJ, 256>>>(dense_w, cls_b, out);
    final_kernel<<<dim3(Bq, 5), 64>>>(dense_b, cls_w, out);
}

// round 14
// speedup vs baseline: 1.0044x; 1.0044x over previous
#include <cuda_runtime.h>
#include <cuda_bf16.h>

// Problem: B=64, L=1024, D=1280
//   pool_len = lengths + 2
//   emb[b,d]  = mean over l < pool_len of prev[b,l,d]
//   x         = relu(emb @ dense_w + dense_b)        [64,1280]
//   out       = x @ cls_w + cls_b                    [64,1]
//
// Two launches:
//  1) pool_kernel : 592 blocks x 320 thr (R11 config, measured 36.7us /
//     4.47 TB/s — best of LDG/TMA/half-width variants). Exact task list over
//     valid 64-row segments; last-arriving block per b reduces partials and
//     writes embT[k][b] (monotonic counters, replay-safe).
//  2) epilogue_kernel : 320 blocks x 256 thr, all co-resident. Phase G =
//     KS=8 k-split FFMA2 GEMM -> grid barrier -> Phase F = k-reduce + bias +
//     relu + cls dot, atomicAdd into out (init'd by block 0 before barrier).

#define Bq     64
#define Lq     1024
#define Dq     1280
#define D4     320           // float4 per row
#define SEGR   64            // rows per pool segment
#define MAXSEG 16
#define GPOOL  592           // pool blocks

#define KS     8             // GEMM k-splits
#define KCH    160           // k per split
#define KC     80            // k staged per chunk
#define NJ     40            // j tiles
#define JTW    32            // j tile width
#define NEPI   320           // epilogue blocks (co-resident: <= 148*3)

typedef unsigned long long u64;

// scratch (allocation-free: __device__ globals)
__device__ float    g_part [Bq * MAXSEG * Dq];  // pool partials (5.24 MB)
__device__ float    g_embT [Dq * Bq];           // emb transposed [k][b]
__device__ float    g_xpart[KS * Bq * Dq];      // GEMM k-partials (2.62 MB)
__device__ unsigned g_cnt  [Bq];                // pool arrival counters

// epilogue grid-barrier state (count returns to 0; phase grows monotonically
// -> replay-safe without reinitialization)
__device__ unsigned g_bar_count = 0;
__device__ unsigned g_bar_phase = 0;

// packed f32x2 FMA (SASS FFMA2)
__device__ __forceinline__ u64 ffma2(u64 a, u64 b, u64 c) {
    u64 d;
    asm("fma.rn.f32x2 %0, %1, %2, %3;" : "=l"(d) : "l"(a), "l"(b), "l"(c));
    return d;
}
__device__ __forceinline__ u64 pack2(float lo, float hi) {
    u64 d;
    asm("mov.b64 %0, {%1, %2};" : "=l"(d) : "f"(lo), "f"(hi));
    return d;
}
__device__ __forceinline__ void unpack2(u64 v, float& lo, float& hi) {
    asm("mov.b64 {%0, %1}, %2;" : "=f"(lo), "=f"(hi) : "l"(v));
}

// ---------------------------------------------------------------------------
// Kernel 1: balanced ragged pool + fused per-b reduction (R11 config).
// ---------------------------------------------------------------------------
__global__ void __launch_bounds__(D4) pool_kernel(
    const float* __restrict__ prev, const int* __restrict__ lengths)
{
    __shared__ int s_pre[Bq + 1];
    __shared__ int s_last;

    const int tid = threadIdx.x;
    const int bid = blockIdx.x;

    if (tid == 0) {
        int acc = 0;
        s_pre[0] = 0;
        for (int b = 0; b < Bq; ++b) {
            int pl = lengths[b] + 2;
            acc += (pl + SEGR - 1) >> 6;          // ceil(pl/64)
            s_pre[b + 1] = acc;
        }
    }
    __syncthreads();
    const int S = s_pre[Bq];                      // total valid segments

    for (int t = bid; t < S; t += GPOOL) {
        // binary search: b with s_pre[b] <= t < s_pre[b+1]
        int lo = 0, hi = Bq;
        while (hi - lo > 1) {
            int m = (lo + hi) >> 1;
            if (s_pre[m] <= t) lo = m; else hi = m;
        }
        const int b    = lo;
        const int seg  = t - s_pre[b];
        const int pl   = lengths[b] + 2;
        const int l0   = seg * SEGR;
        const int n    = min(SEGR, pl - l0);      // >= 1 by construction
        const int nseg = s_pre[b + 1] - s_pre[b];

        float4 a0 = make_float4(0.f, 0.f, 0.f, 0.f);
        float4 a1 = a0, a2 = a0, a3 = a0;

        const float4* __restrict__ p =
            reinterpret_cast<const float4*>(prev) + ((size_t)b * Lq + l0) * D4 + tid;
        int l = 0;
        for (; l + 8 <= n; l += 8) {
            float4 v0 = p[(size_t)(l + 0) * D4];
            float4 v1 = p[(size_t)(l + 1) * D4];
            float4 v2 = p[(size_t)(l + 2) * D4];
            float4 v3 = p[(size_t)(l + 3) * D4];
            float4 v4 = p[(size_t)(l + 4) * D4];
            float4 v5 = p[(size_t)(l + 5) * D4];
            float4 v6 = p[(size_t)(l + 6) * D4];
            float4 v7 = p[(size_t)(l + 7) * D4];
            a0.x += v0.x; a0.y += v0.y; a0.z += v0.z; a0.w += v0.w;
            a1.x += v1.x; a1.y += v1.y; a1.z += v1.z; a1.w += v1.w;
            a2.x += v2.x; a2.y += v2.y; a2.z += v2.z; a2.w += v2.w;
            a3.x += v3.x; a3.y += v3.y; a3.z += v3.z; a3.w += v3.w;
            a0.x += v4.x; a0.y += v4.y; a0.z += v4.z; a0.w += v4.w;
            a1.x += v5.x; a1.y += v5.y; a1.z += v5.z; a1.w += v5.w;
            a2.x += v6.x; a2.y += v6.y; a2.z += v6.z; a2.w += v6.w;
            a3.x += v7.x; a3.y += v7.y; a3.z += v7.z; a3.w += v7.w;
        }
        for (; l < n; ++l) {
            float4 v = p[(size_t)l * D4];
            a0.x += v.x; a0.y += v.y; a0.z += v.z; a0.w += v.w;
        }
        float4 s;
        s.x = (a0.x + a1.x) + (a2.x + a3.x);
        s.y = (a0.y + a1.y) + (a2.y + a3.y);
        s.z = (a0.z + a1.z) + (a2.z + a3.z);
        s.w = (a0.w + a1.w) + (a2.w + a3.w);
        reinterpret_cast<float4*>(g_part)[((size_t)b * MAXSEG + seg) * D4 + tid] = s;

        // publish partial, count arrival; last arrival reduces this b
        __threadfence();
        __syncthreads();
        if (tid == 0) {
            unsigned old = atomicAdd(&g_cnt[b], 1u);
            s_last = (((old + 1u) % (unsigned)nseg) == 0u) ? 1 : 0;
        }
        __syncthreads();
        if (s_last) {
            __threadfence();   // acquire other blocks' partials
            const float4* gp = reinterpret_cast<const float4*>(g_part)
                               + (size_t)b * MAXSEG * D4 + tid;
            float4 r = make_float4(0.f, 0.f, 0.f, 0.f);
            for (int sg = 0; sg < nseg; ++sg) {
                float4 v = gp[(size_t)sg * D4];
                r.x += v.x; r.y += v.y; r.z += v.z; r.w += v.w;
            }
            const float inv = 1.0f / (float)pl;
            r.x *= inv; r.y *= inv; r.z *= inv; r.w *= inv;
            g_embT[(size_t)(4 * tid + 0) * Bq + b] = r.x;
            g_embT[(size_t)(4 * tid + 1) * Bq + b] = r.y;
            g_embT[(size_t)(4 * tid + 2) * Bq + b] = r.z;
            g_embT[(size_t)(4 * tid + 3) * Bq + b] = r.w;
        }
        __syncthreads();       // protect s_last across task iterations
    }
}

// ---------------------------------------------------------------------------
// Kernel 2: fused GEMM + final. 320 blocks x 256 thr, all co-resident.
// ---------------------------------------------------------------------------
__global__ void __launch_bounds__(256, 3) epilogue_kernel(
    const float* __restrict__ W,
    const float* __restrict__ dense_b,
    const float* __restrict__ cls_w,
    const float* __restrict__ cls_b,
    float*       __restrict__ out)
{
    __shared__ __align__(16) float sE[KC][Bq];    // 20 KB
    __shared__ __align__(16) float sW[KC][JTW];   // 10 KB

    const int bid = blockIdx.x;
    const int tid = threadIdx.x;

    // ---- Phase G: k-split GEMM (KS=8), FFMA2, tile 64b x 32j x 160k ----
    {
        const int ky = bid / NJ;                  // 0..7
        const int jx = bid % NJ;                  // 0..39
        const int k0 = ky * KCH;
        const int j0 = jx * JTW;
        const int bg = tid >> 3;                  // 0..31 -> b = 2bg, 2bg+1
        const int jg = tid & 7;                   // 0..7  -> j = 4jg..4jg+3

        if (bid == 0 && tid < Bq)                 // init out for phase F atomics
            out[tid] = cls_b[0];

        u64 a00 = 0ull, a01 = 0ull, a10 = 0ull, a11 = 0ull;

        for (int c = 0; c < KCH; c += KC) {
            __syncthreads();
            for (int i = tid; i < KC * Bq; i += 256) {
                int kk = i >> 6;
                int bb = i & 63;
                sE[kk][bb] = g_embT[(size_t)(k0 + c + kk) * Bq + bb];
            }
            for (int i = tid; i < KC * JTW; i += 256) {
                int kk = i >> 5;
                int jj = i & 31;
                sW[kk][jj] = W[(size_t)(k0 + c + kk) * Dq + j0 + jj];
            }
            __syncthreads();

#pragma unroll 10
            for (int kk = 0; kk < KC; ++kk) {
                float2 e  = *reinterpret_cast<const float2*>(&sE[kk][2 * bg]);
                float4 w  = *reinterpret_cast<const float4*>(&sW[kk][4 * jg]);
                u64 e0  = pack2(e.x, e.x);
                u64 e1  = pack2(e.y, e.y);
                u64 w01 = pack2(w.x, w.y);
                u64 w23 = pack2(w.z, w.w);
                a00 = ffma2(e0, w01, a00);
                a01 = ffma2(e0, w23, a01);
                a10 = ffma2(e1, w01, a10);
                a11 = ffma2(e1, w23, a11);
            }
        }

        float x0, y0, z0, w0f, x1, y1, z1, w1f;
        unpack2(a00, x0, y0); unpack2(a01, z0, w0f);
        unpack2(a10, x1, y1); unpack2(a11, z1, w1f);
        const int b0 = 2 * bg;
        float* dst0 = &g_xpart[((size_t)ky * Bq + b0) * Dq + j0 + 4 * jg];
        *reinterpret_cast<float4*>(dst0)      = make_float4(x0, y0, z0, w0f);
        *reinterpret_cast<float4*>(dst0 + Dq) = make_float4(x1, y1, z1, w1f);
    }

    // ---- grid barrier over all 320 blocks (release/acquire via fences) ----
    __syncthreads();
    if (tid == 0) {
        __threadfence();
        unsigned ph = *(volatile unsigned*)&g_bar_phase;
        __threadfence();
        if (atomicAdd(&g_bar_count, 1u) == NEPI - 1u) {
            *(volatile unsigned*)&g_bar_count = 0u;
            __threadfence();
            atomicAdd(&g_bar_phase, 1u);          // release
        } else {
            while (*(volatile unsigned*)&g_bar_phase == ph) __nanosleep(64);
        }
        __threadfence();
    }
    __syncthreads();

    // ---- Phase F: k-reduce + bias + relu + cls dot; atomicAdd into out ----
    if (tid < 64) {
        const int b  = bid & 63;
        const int d4 = (bid >> 6) * 64 + tid;     // 0..319
        const float4* xp = reinterpret_cast<const float4*>(g_xpart);

        float4 s = reinterpret_cast<const float4*>(dense_b)[d4];
#pragma unroll
        for (int ks = 0; ks < KS; ++ks) {
            float4 v = xp[((size_t)ks * Bq + b) * D4 + d4];
            s.x += v.x; s.y += v.y; s.z += v.z; s.w += v.w;
        }
        s.x = fmaxf(s.x, 0.f); s.y = fmaxf(s.y, 0.f);
        s.z = fmaxf(s.z, 0.f); s.w = fmaxf(s.w, 0.f);

        float4 w = reinterpret_cast<const float4*>(cls_w)[d4];
        float part = s.x * w.x + s.y * w.y + s.z * w.z + s.w * w.w;

#pragma unroll
        for (int o = 16; o > 0; o >>= 1)
            part += __shfl_down_sync(0xffffffffu, part, o);
        if ((tid & 31) == 0)
            atomicAdd(&out[b], part);             // 10 adds per b total
    }
}

// ---------------------------------------------------------------------------
extern "C" void kernel_launch(void* const* d_in, const int* in_sizes, int n_in,
                              void* d_out, int out_size)
{
    const float* prev    = (const float*)d_in[0];
    const int*   lengths = (const int*)  d_in[1];
    const float* dense_w = (const float*)d_in[2];
    const float* dense_b = (const float*)d_in[3];
    const float* cls_w   = (const float*)d_in[4];
    const float* cls_b   = (const float*)d_in[5];
    float*       out     = (float*)d_out;

    pool_kernel    <<<GPOOL, D4>>>(prev, lengths);
    epilogue_kernel<<<NEPI, 256>>>(dense_w, dense_b, cls_w, cls_b, out);
}